// round 4
// baseline (speedup 1.0000x reference)
#include <cuda_runtime.h>
#include <cstddef>

// TokenEmbedding segment-sum, GB300 sm_103a.
// sequence_output: [B, L, H] f32, wordpiece_to_token: [B, L] i32 (sorted per batch)
// out[b, j, :] = sum over p with seg[b,p]==j of x[b, p, :]
//
// Gather formulation: segment ids are sorted, so token j's wordpieces are the
// contiguous range [lower_bound(j), lower_bound(j+1)). One block per (token, batch),
// 192 threads = one float4 lane each (H=768 -> 192 float4). Every output element
// is written exactly once (zero for empty ranges), so no zero-init pass and no atomics.

constexpr int B = 16;
constexpr int L = 4096;
constexpr int H = 768;
constexpr int V = H / 4; // 192 float4 per row

__global__ __launch_bounds__(V) void token_segsum_kernel(
    const float4* __restrict__ x,   // [B, L, V]
    const int*    __restrict__ seg, // [B, L]
    float4*       __restrict__ out) // [B, L, V]
{
    const int j = blockIdx.x;   // token index
    const int b = blockIdx.y;   // batch
    const int* __restrict__ s = seg + b * L;

    // lower_bound(j): first p with s[p] >= j
    int lo = 0, hi = L;
    #pragma unroll 1
    while (lo < hi) {
        int mid = (lo + hi) >> 1;
        if (__ldg(s + mid) < j) lo = mid + 1; else hi = mid;
    }
    const int start = lo;
    // upper_bound(j): first p with s[p] > j   (continue from start)
    hi = L;
    #pragma unroll 1
    while (lo < hi) {
        int mid = (lo + hi) >> 1;
        if (__ldg(s + mid) <= j) lo = mid + 1; else hi = mid;
    }
    const int end = lo;

    const int col = threadIdx.x; // 0..191
    const float4* __restrict__ base = x + (size_t)b * L * V;

    float4 acc = make_float4(0.f, 0.f, 0.f, 0.f);
    #pragma unroll 1
    for (int p = start; p < end; ++p) {
        float4 v = __ldg(base + (size_t)p * V + col);
        acc.x += v.x; acc.y += v.y; acc.z += v.z; acc.w += v.w;
    }

    out[(size_t)b * L * V + (size_t)j * V + col] = acc;
}

extern "C" void kernel_launch(void* const* d_in, const int* in_sizes, int n_in,
                              void* d_out, int out_size)
{
    const float4* x   = (const float4*)d_in[0];
    const int*    seg = (const int*)d_in[1];
    float4*       out = (float4*)d_out;

    dim3 grid(L, B);
    token_segsum_kernel<<<grid, V>>>(x, seg, out);
}

// round 6
// speedup vs baseline: 2.5703x; 2.5703x over previous
#include <cuda_runtime.h>
#include <cstddef>

// TokenEmbedding segment-sum, GB300 sm_103a — R4.
// Two-phase: (1) scatter-build per-token boundary table from the sorted segment
// ids, (2) gather-sum with zero search cost, T=4 tokens per block for contiguous
// streaming and fewer blocks. No atomics, no zero-init pass, no __syncthreads.

constexpr int B = 16;
constexpr int L = 4096;
constexpr int H = 768;
constexpr int V = H / 4;   // 192 float4 per row
constexpr int T = 4;       // tokens per block

// bnd[b][j] = first wordpiece p with seg[b][p] >= j, for j in [0, L]
__device__ int g_bnd[B][L + 1];

__global__ __launch_bounds__(256) void boundaries_kernel(const int* __restrict__ seg)
{
    const int idx = blockIdx.x * blockDim.x + threadIdx.x;
    if (idx >= B * L) return;
    const int b = idx >> 12;        // / L
    const int p = idx & (L - 1);    // % L
    const int* __restrict__ s = seg + b * L;

    const int sp    = __ldg(s + p);
    const int sprev = (p == 0) ? -1 : __ldg(s + p - 1);

    // All j in (sprev, sp] have lower_bound == p
    for (int j = sprev + 1; j <= sp; ++j)
        g_bnd[b][j] = p;

    // Tail: all j in (seg[L-1], L] have lower_bound == L
    if (p == L - 1)
        for (int j = sp + 1; j <= L; ++j)
            g_bnd[b][j] = L;
}

__global__ __launch_bounds__(V) void token_segsum_kernel(
    const float4* __restrict__ x,   // [B, L, V]
    float4*       __restrict__ out) // [B, L, V]
{
    const int b   = blockIdx.y;
    const int j0  = blockIdx.x * T;
    const int col = threadIdx.x;    // 0..191

    const float4* __restrict__ base  = x   + (size_t)b * L * V;
    float4*       __restrict__ obase = out + (size_t)b * L * V;

    // Uniform boundary reads (broadcast within the block, L1/L2-hot)
    int bnd[T + 1];
    #pragma unroll
    for (int t = 0; t <= T; ++t)
        bnd[t] = __ldg(&g_bnd[b][j0 + t]);

    #pragma unroll
    for (int t = 0; t < T; ++t) {
        float4 acc = make_float4(0.f, 0.f, 0.f, 0.f);
        #pragma unroll 1
        for (int p = bnd[t]; p < bnd[t + 1]; ++p) {
            float4 v = __ldg(base + (size_t)p * V + col);
            acc.x += v.x; acc.y += v.y; acc.z += v.z; acc.w += v.w;
        }
        obase[(size_t)(j0 + t) * V + col] = acc;
    }
}

extern "C" void kernel_launch(void* const* d_in, const int* in_sizes, int n_in,
                              void* d_out, int out_size)
{
    const float4* x   = (const float4*)d_in[0];
    const int*    seg = (const int*)d_in[1];
    float4*       out = (float4*)d_out;

    boundaries_kernel<<<(B * L + 255) / 256, 256>>>(seg);

    dim3 grid(L / T, B);
    token_segsum_kernel<<<grid, V>>>(x, out);
}

// round 7
// speedup vs baseline: 2.6488x; 1.0306x over previous
#include <cuda_runtime.h>
#include <cstddef>

// TokenEmbedding segment-sum, GB300 sm_103a — R6.
// Phase 1: scatter-build boundary table bnd[b][j] = lower_bound(seg_b, j).
// Phase 2: one block per (batch, 4 tokens). The block streams the CONTIGUOUS
// wordpiece range [bnd[j0], bnd[j0+4]) with a 2-deep load pipeline (independent
// LDG.128 addresses -> MLP>=2 per warp) and routes each row into one of four
// register accumulators via block-uniform branches (seg value is uniform across
// the block: only the column varies per thread). No atomics, no zero-init pass.

constexpr int B = 16;
constexpr int L = 4096;
constexpr int H = 768;
constexpr int V = H / 4;   // 192 float4 per row
constexpr int T = 4;       // tokens per block

// bnd[b][j] = first wordpiece p with seg[b][p] >= j, for j in [0, L]
__device__ int g_bnd[B][L + 1];

__global__ __launch_bounds__(256) void boundaries_kernel(const int* __restrict__ seg)
{
    const int idx = blockIdx.x * blockDim.x + threadIdx.x;
    if (idx >= B * L) return;
    const int b = idx >> 12;        // / L
    const int p = idx & (L - 1);    // % L
    const int* __restrict__ s = seg + b * L;

    const int sp    = __ldg(s + p);
    const int sprev = (p == 0) ? -1 : __ldg(s + p - 1);

    for (int j = sprev + 1; j <= sp; ++j)
        g_bnd[b][j] = p;

    if (p == L - 1)
        for (int j = sp + 1; j <= L; ++j)
            g_bnd[b][j] = L;
}

__device__ __forceinline__ void accum(float4& a, const float4& v)
{
    a.x += v.x; a.y += v.y; a.z += v.z; a.w += v.w;
}

__global__ __launch_bounds__(V) void token_segsum_kernel(
    const float4* __restrict__ x,   // [B, L, V]
    const int*    __restrict__ seg, // [B, L]
    float4*       __restrict__ out) // [B, L, V]
{
    const int b   = blockIdx.y;
    const int j0  = blockIdx.x * T;
    const int col = threadIdx.x;    // 0..191

    const float4* __restrict__ base  = x   + (size_t)b * L * V + col;
    float4*       __restrict__ obase = out + (size_t)b * L * V + (size_t)j0 * V + col;
    const int*    __restrict__ s     = seg + b * L;

    const int start = __ldg(&g_bnd[b][j0]);
    const int end   = __ldg(&g_bnd[b][j0 + T]);

    float4 a0 = make_float4(0.f, 0.f, 0.f, 0.f);
    float4 a1 = a0, a2 = a0, a3 = a0;

    int p = start;
    #pragma unroll 1
    for (; p + 1 < end; p += 2) {
        // Two independent loads issued before any consumption -> MLP >= 2.
        float4 v0 = __ldg(base + (size_t)p * V);
        float4 v1 = __ldg(base + (size_t)(p + 1) * V);
        int t0 = __ldg(s + p)     - j0;   // uniform across block
        int t1 = __ldg(s + p + 1) - j0;

        if      (t0 == 0) accum(a0, v0);
        else if (t0 == 1) accum(a1, v0);
        else if (t0 == 2) accum(a2, v0);
        else              accum(a3, v0);

        if      (t1 == 0) accum(a0, v1);
        else if (t1 == 1) accum(a1, v1);
        else if (t1 == 2) accum(a2, v1);
        else              accum(a3, v1);
    }
    if (p < end) {
        float4 v0 = __ldg(base + (size_t)p * V);
        int t0 = __ldg(s + p) - j0;
        if      (t0 == 0) accum(a0, v0);
        else if (t0 == 1) accum(a1, v0);
        else if (t0 == 2) accum(a2, v0);
        else              accum(a3, v0);
    }

    obase[0 * V] = a0;
    obase[1 * V] = a1;
    obase[2 * V] = a2;
    obase[3 * V] = a3;
}

extern "C" void kernel_launch(void* const* d_in, const int* in_sizes, int n_in,
                              void* d_out, int out_size)
{
    const float4* x   = (const float4*)d_in[0];
    const int*    seg = (const int*)d_in[1];
    float4*       out = (float4*)d_out;

    boundaries_kernel<<<(B * L + 255) / 256, 256>>>(seg);

    dim3 grid(L / T, B);
    token_segsum_kernel<<<grid, V>>>(x, seg, out);
}